// round 11
// baseline (speedup 1.0000x reference)
#include <cuda_runtime.h>
#include <cuda_bf16.h>
#include <cuda_fp8.h>
#include <cstdint>

// ============================================================================
// DendriticResidualModel — mma.sync FP8 e4m3 (K=384, B scaled x16) +
// register-level softplus tree epilogue.
//   pre[bt,j] = x·Wa^T + iv·Wi^T + temb·Wt^T + ba,  t = bt & 127
//   Tree weights contract GEMM error ~1e-4 -> fp8 gives ~5e-6 output error.
// ============================================================================

#define NUM_NODES 16384
#define BT_ROWS   2048
#define K8        384         // K in fp8 bytes
#define KC_CHUNKS 3           // 384 / 128
#define STAGE_B   32768       // A 16KB + B 16KB per stage (128 rows x 128B each)
#define NSTAGE    2

// epilogue smem region offsets (bytes from dynamic smem base)
#define EOFF_TP3  65536       // 128 * 144 = 18432
#define EOFF_TP2  83968       // 128 * 48  = 6144
#define EOFF_TP1  90112       // 128 * 16  = 2048
#define EOFF_W3   92160       // 512
#define EOFF_BA   92672       // 512
#define EOFF_W2   93184       // 128
#define EOFF_W1   93312       // 32
#define SMEM_REQ  93344

__device__ __align__(16) uint8_t g_A8[BT_ROWS * K8];        // 0.75 MB (e4m3)
__device__ __align__(16) uint8_t g_B8[NUM_NODES * K8];      // 6.3 MB  (e4m3, x16)
__device__ __align__(16) float g_tp3[128 * 4096];
__device__ __align__(16) float g_tp2[128 * 1024];
__device__ __align__(16) float g_tp1[128 * 256];

// ---------------------------------------------------------------- helpers
__device__ __forceinline__ uint32_t smem_u32(const void* p) {
    uint32_t a;
    asm("{ .reg .u64 t; cvta.to.shared.u64 t, %1; cvt.u32.u64 %0, t; }" : "=r"(a) : "l"(p));
    return a;
}
__device__ __forceinline__ void cp_async16(uint32_t dst, const void* src) {
    asm volatile("cp.async.cg.shared.global [%0], [%1], 16;" :: "r"(dst), "l"(src));
}
__device__ __forceinline__ void cp_async8(uint32_t dst, const void* src) {
    asm volatile("cp.async.ca.shared.global [%0], [%1], 8;" :: "r"(dst), "l"(src));
}
__device__ __forceinline__ void ldsm_x4(uint32_t* r, uint32_t addr) {
    asm volatile("ldmatrix.sync.aligned.m8n8.x4.shared.b16 {%0,%1,%2,%3}, [%4];"
                 : "=r"(r[0]), "=r"(r[1]), "=r"(r[2]), "=r"(r[3]) : "r"(addr));
}
// fp8 m16n8k32: fragment is the byte-reinterpretation of f16 m16n8k16 frags.
__device__ __forceinline__ void mma16832(float* d, const uint32_t* a, const uint32_t* b) {
    asm volatile(
        "mma.sync.aligned.m16n8k32.row.col.f32.e4m3.e4m3.f32 "
        "{%0,%1,%2,%3}, {%4,%5,%6,%7}, {%8,%9}, {%0,%1,%2,%3};"
        : "+f"(d[0]), "+f"(d[1]), "+f"(d[2]), "+f"(d[3])
        : "r"(a[0]), "r"(a[1]), "r"(a[2]), "r"(a[3]), "r"(b[0]), "r"(b[1]));
}
__device__ __forceinline__ float softplus_f(float x) {
    float e = exp2f(fabsf(x) * -1.44269504f);
    return fmaxf(x, 0.0f) + 0.69314718f * __log2f(1.0f + e);
}

// ----------------------------------------------------------- prep kernels
// 4 rows per block, 96 threads per row; each thread: float4 load -> fp8x4 store
__global__ void __launch_bounds__(384)
convA_kernel(const float* __restrict__ x, const float* __restrict__ iv,
             const float* __restrict__ temb)
{
    const int tid = threadIdx.x;
    const int r  = tid / 96;
    const int c  = (tid - r * 96) * 4;
    const int bt = blockIdx.x * 4 + r;
    float4 v;
    if (c < 256)      v = *(const float4*)(x + bt * 256 + c);
    else if (c < 320) v = *(const float4*)(iv + bt * 64 + (c - 256));
    else              v = *(const float4*)(temb + (bt & 127) * 64 + (c - 320));
    __nv_fp8x4_e4m3 q(v);
    *(uint32_t*)(g_A8 + (size_t)bt * K8 + c) = *(uint32_t*)&q;
}

__global__ void __launch_bounds__(384)
convB_kernel(const float* __restrict__ Wa, const float* __restrict__ Wi,
             const float* __restrict__ Wt)
{
    const int tid = threadIdx.x;
    const int r = tid / 96;
    const int c = (tid - r * 96) * 4;
    const int j = blockIdx.x * 4 + r;
    float4 v;
    if (c < 256)      v = *(const float4*)(Wa + (size_t)j * 256 + c);
    else if (c < 320) v = *(const float4*)(Wi + (size_t)j * 64 + (c - 256));
    else              v = *(const float4*)(Wt + (size_t)j * 64 + (c - 320));
    v.x *= 16.f; v.y *= 16.f; v.z *= 16.f; v.w *= 16.f;   // scale into e4m3 sweet spot
    __nv_fp8x4_e4m3 q(v);
    *(uint32_t*)(g_B8 + (size_t)j * K8 + c) = *(uint32_t*)&q;
}

__global__ void __launch_bounds__(128)
precompute_kernel(const float* __restrict__ temb,
                  const float* __restrict__ tW3, const float* __restrict__ tb3,
                  const float* __restrict__ tW2, const float* __restrict__ tb2,
                  const float* __restrict__ tW1, const float* __restrict__ tb1)
{
    __shared__ __align__(16) float semb[16 * 64];
    const int tid = threadIdx.x;
    const int t0  = blockIdx.y * 16;
    for (int i = tid; i < 256; i += 128)
        ((float4*)semb)[i] = ((const float4*)(temb + t0 * 64))[i];
    __syncthreads();

    const int col = blockIdx.x * 128 + tid;   // 0..5375
    const float* wrow; float bias; float* outb; int ostride;
    if (col < 4096)      { wrow = tW3 + col * 64; bias = tb3[col]; outb = g_tp3 + col; ostride = 4096; }
    else if (col < 5120) { int c = col - 4096; wrow = tW2 + c * 64; bias = tb2[c]; outb = g_tp2 + c; ostride = 1024; }
    else                 { int c = col - 5120; wrow = tW1 + c * 64; bias = tb1[c]; outb = g_tp1 + c; ostride = 256;  }

    float w[64];
    #pragma unroll
    for (int i = 0; i < 16; i++) ((float4*)w)[i] = ((const float4*)wrow)[i];

    for (int tt = 0; tt < 16; tt++) {
        const float* e = semb + tt * 64;
        float a0 = bias, a1 = 0.f, a2 = 0.f, a3 = 0.f;
        #pragma unroll
        for (int k = 0; k < 64; k += 4) {
            a0 += e[k] * w[k];     a1 += e[k+1] * w[k+1];
            a2 += e[k+2] * w[k+2]; a3 += e[k+3] * w[k+3];
        }
        outb[(size_t)(t0 + tt) * ostride] = (a0 + a1) + (a2 + a3);
    }
}

// ------------------------------------------------------------ main kernel
// grid (128 n-tiles, 16 m-tiles), 256 threads; CTA tile 128x128, K=384 fp8.
// K-chunk = 128 bytes; 2-stage cp.async pipeline, 2 CTAs/SM.
__global__ void __launch_bounds__(256, 2)
main_kernel(const float* __restrict__ w3, const float* __restrict__ w2,
            const float* __restrict__ w1, const float* __restrict__ ba,
            float* __restrict__ out)
{
    extern __shared__ char dyn_smem[];
    const uint32_t smb = smem_u32(dyn_smem);

    const int tid  = threadIdx.x;
    const int lane = tid & 31, wid = tid >> 5;
    const int warp_m = wid & 3, warp_n = wid >> 2;
    const int j0  = blockIdx.x * 128;
    const int bt0 = blockIdx.y * 128;
    const int node0 = blockIdx.x * 2;

    // ---- stage epilogue tables (joins cp.async group 0) ----
    {
        #pragma unroll
        for (int q = 0; q < 4; q++) {               // tp3: 1024 x cp16
            int id = tid + q * 256;
            int t = id >> 3, nl = (id >> 2) & 1, sub = id & 3;
            cp_async16(smb + EOFF_TP3 + t * 144 + nl * 64 + sub * 16,
                       g_tp3 + (size_t)t * 4096 + (node0 + nl) * 16 + sub * 4);
        }
        {                                           // tp2: 256 x cp16
            int t = tid >> 1, nl = tid & 1;
            cp_async16(smb + EOFF_TP2 + t * 48 + nl * 16,
                       g_tp2 + (size_t)t * 1024 + (node0 + nl) * 4);
        }
        if (tid < 128)                              // tp1: 128 x cp8
            cp_async8(smb + EOFF_TP1 + tid * 16, g_tp1 + (size_t)tid * 256 + node0);
        if (tid >= 128 && tid < 160)                // w3 slice: 128 f
            cp_async16(smb + EOFF_W3 + (tid - 128) * 16, w3 + node0 * 64 + (tid - 128) * 4);
        if (tid >= 160 && tid < 192)                // ba slice: 128 f
            cp_async16(smb + EOFF_BA + (tid - 160) * 16, ba + j0 + (tid - 160) * 4);
        if (tid >= 192 && tid < 200)                // w2 slice: 32 f
            cp_async16(smb + EOFF_W2 + (tid - 192) * 16, w2 + node0 * 16 + (tid - 192) * 4);
        if (tid >= 200 && tid < 202)                // w1 slice: 8 f
            cp_async16(smb + EOFF_W1 + (tid - 200) * 16, w1 + node0 * 4 + (tid - 200) * 4);
    }

    // ---- stage loader: 128 fp8 K-cols; A/B 128 rows x 128B, swizzled ----
    auto load_stage = [&](int kc, int s) {
        const uint32_t base = smb + s * STAGE_B;
        const int kof = kc * 128;
        #pragma unroll
        for (int q = 0; q < 4; q++) {               // A
            int id = tid + q * 256;
            int row = id >> 3, ch = id & 7;
            cp_async16(base + row * 128 + ((ch ^ (row & 7)) * 16),
                       g_A8 + (size_t)(bt0 + row) * K8 + kof + ch * 16);
        }
        #pragma unroll
        for (int q = 0; q < 4; q++) {               // B
            int id = tid + q * 256;
            int row = id >> 3, ch = id & 7;
            cp_async16(base + 16384 + row * 128 + ((ch ^ (row & 7)) * 16),
                       g_B8 + (size_t)(j0 + row) * K8 + kof + ch * 16);
        }
        asm volatile("cp.async.commit_group;" ::: "memory");
    };

    load_stage(0, 0);
    load_stage(1, 1);

    float acc[2][8][4];
    #pragma unroll
    for (int mg = 0; mg < 2; mg++)
        #pragma unroll
        for (int ng = 0; ng < 8; ng++)
            #pragma unroll
            for (int r = 0; r < 4; r++) acc[mg][ng][r] = 0.f;

    const int a_row = warp_m * 32 + (lane & 15);
    const int a_half = (lane >> 4) & 1;
    const int b_row = warp_n * 64 + ((lane >> 4) & 1) * 8 + (lane & 7);
    const int b_half = (lane >> 3) & 1;

    for (int kc = 0; kc < KC_CHUNKS; kc++) {
        if (kc < KC_CHUNKS - 1) asm volatile("cp.async.wait_group 1;" ::: "memory");
        else                    asm volatile("cp.async.wait_group 0;" ::: "memory");
        __syncthreads();

        const uint32_t sA = smb + (kc & 1) * STAGE_B;
        const uint32_t sB = sA + 16384;
        #pragma unroll
        for (int kk = 0; kk < 4; kk++) {            // each kk covers k32 (fp8)
            uint32_t af[2][4], bf[4][4];
            #pragma unroll
            for (int mg = 0; mg < 2; mg++) {
                int row = a_row + mg * 16;
                ldsm_x4(af[mg], sA + row * 128 + (((kk * 2 + a_half) ^ (row & 7)) * 16));
            }
            #pragma unroll
            for (int n2 = 0; n2 < 4; n2++) {
                int row = b_row + n2 * 16;
                ldsm_x4(bf[n2], sB + row * 128 + (((kk * 2 + b_half) ^ (row & 7)) * 16));
            }
            #pragma unroll
            for (int mg = 0; mg < 2; mg++)
                #pragma unroll
                for (int ng = 0; ng < 8; ng++)
                    mma16832(acc[mg][ng], af[mg], bf[ng >> 1] + (ng & 1) * 2);
        }
        __syncthreads();
        if (kc + 2 < KC_CHUNKS) load_stage(kc + 2, kc & 1);
    }

    // ---- register-level tree epilogue (acc carries 16x pre; descale 1/16) ----
    const float* sTP3 = (const float*)(dyn_smem + EOFF_TP3);
    const float* sTP2 = (const float*)(dyn_smem + EOFF_TP2);
    const float* sTP1 = (const float*)(dyn_smem + EOFF_TP1);
    const float* sW3  = (const float*)(dyn_smem + EOFF_W3);
    const float* sBA  = (const float*)(dyn_smem + EOFF_BA);
    const float* sW2  = (const float*)(dyn_smem + EOFF_W2);
    const float* sW1  = (const float*)(dyn_smem + EOFF_W1);

    const int b_  = (lane >> 1) & 1;
    const int q_  = lane >> 2;
    float res[4];

    #pragma unroll
    for (int mg = 0; mg < 2; mg++)
        #pragma unroll
        for (int h = 0; h < 2; h++) {
            const int row = warp_m * 32 + mg * 16 + h * 8 + q_;   // == t for this bt
            float a3loc[8];
            #pragma unroll
            for (int ng = 0; ng < 8; ng++) {
                int col0 = warp_n * 64 + ng * 8 + 2 * (lane & 3);
                float p = sW3[col0]     * softplus_f(fmaf(acc[mg][ng][h * 2],     0.0625f, sBA[col0]))
                        + sW3[col0 + 1] * softplus_f(fmaf(acc[mg][ng][h * 2 + 1], 0.0625f, sBA[col0 + 1]));
                p += __shfl_xor_sync(0xffffffffu, p, 1);
                a3loc[ng] = softplus_f(p + sTP3[row * 36 + warp_n * 16 + 2 * ng + b_]);
            }
            float a2v[4];
            #pragma unroll
            for (int i3 = 0; i3 < 4; i3++) {
                float p = sW2[warp_n * 16 + i3 * 4 + b_]     * a3loc[2 * i3]
                        + sW2[warp_n * 16 + i3 * 4 + 2 + b_] * a3loc[2 * i3 + 1];
                p += __shfl_xor_sync(0xffffffffu, p, 2);
                a2v[i3] = softplus_f(p + sTP2[row * 12 + warp_n * 4 + i3]);
            }
            float s = sTP1[row * 4 + warp_n];
            #pragma unroll
            for (int i3 = 0; i3 < 4; i3++) s += sW1[warp_n * 4 + i3] * a2v[i3];
            res[mg * 2 + h] = softplus_f(s);
        }

    const int sel = lane & 3;
    const int rowsel = warp_m * 32 + (sel >> 1) * 16 + (sel & 1) * 8 + q_;
    out[(size_t)(bt0 + rowsel) * 256 + node0 + warp_n] = res[sel];
}

// ---------------------------------------------------------------------------
extern "C" void kernel_launch(void* const* d_in, const int* in_sizes, int n_in,
                              void* d_out, int out_size)
{
    const float* x    = (const float*)d_in[0];
    const float* temb = (const float*)d_in[1];
    const float* iv   = (const float*)d_in[2];
    const float* Wa   = (const float*)d_in[3];
    const float* ba   = (const float*)d_in[4];
    const float* Wt   = (const float*)d_in[5];
    const float* Wi   = (const float*)d_in[6];
    const float* w3   = (const float*)d_in[7];
    const float* tW3  = (const float*)d_in[8];
    const float* tb3  = (const float*)d_in[9];
    const float* w2   = (const float*)d_in[10];
    const float* tW2  = (const float*)d_in[11];
    const float* tb2  = (const float*)d_in[12];
    const float* w1   = (const float*)d_in[13];
    const float* tW1  = (const float*)d_in[14];
    const float* tb1  = (const float*)d_in[15];
    float* out = (float*)d_out;

    static bool attr_set = false;
    if (!attr_set) {
        cudaFuncSetAttribute(main_kernel, cudaFuncAttributeMaxDynamicSharedMemorySize, SMEM_REQ);
        attr_set = true;
    }

    convA_kernel<<<BT_ROWS / 4, 384>>>(x, iv, temb);
    convB_kernel<<<NUM_NODES / 4, 384>>>(Wa, Wi, Wt);
    precompute_kernel<<<dim3(42, 8), 128>>>(temb, tW3, tb3, tW2, tb2, tW1, tb1);
    main_kernel<<<dim3(128, 16), 256, SMEM_REQ>>>(w3, w2, w1, ba, out);
}

// round 12
// speedup vs baseline: 1.0379x; 1.0379x over previous
#include <cuda_runtime.h>
#include <cuda_bf16.h>
#include <cstdint>

// ============================================================================
// DendriticResidualModel — mma.sync bf16 (K=384), 3-stage cp.async pipeline,
// late-loaded epilogue tables, register-level softplus tree epilogue.
//   pre[bt,j] = x·Wa^T + iv·Wi^T + temb·Wt^T + ba,  t = bt & 127
// ============================================================================

#define NUM_NODES 16384
#define BT_ROWS   2048
#define K2        384
#define KC_CHUNKS 6           // 384 / 64
#define STAGE_B   32768       // A 16KB + B 16KB per stage
#define NSTAGE    3
#define SMEM_REQ  (NSTAGE * STAGE_B)   // 98304

// epilogue tables live in stage-0 region (loaded after GEMM drains it)
#define EOFF_TP3  0           // 128 * 144 = 18432
#define EOFF_TP2  18432       // 128 * 48  = 6144
#define EOFF_TP1  24576       // 128 * 16  = 2048
#define EOFF_W3   26624       // 512
#define EOFF_BA   27136       // 512
#define EOFF_W2   27648       // 128
#define EOFF_W1   27776       // 32

__device__ __align__(16) __nv_bfloat16 g_A2[BT_ROWS * K2];      // 1.5 MB
__device__ __align__(16) __nv_bfloat16 g_B2[NUM_NODES * K2];    // 12.6 MB
__device__ __align__(16) float g_tp3[128 * 4096];
__device__ __align__(16) float g_tp2[128 * 1024];
__device__ __align__(16) float g_tp1[128 * 256];

// ---------------------------------------------------------------- helpers
__device__ __forceinline__ uint32_t smem_u32(const void* p) {
    uint32_t a;
    asm("{ .reg .u64 t; cvta.to.shared.u64 t, %1; cvt.u32.u64 %0, t; }" : "=r"(a) : "l"(p));
    return a;
}
__device__ __forceinline__ void cp_async16(uint32_t dst, const void* src) {
    asm volatile("cp.async.cg.shared.global [%0], [%1], 16;" :: "r"(dst), "l"(src));
}
__device__ __forceinline__ void cp_async8(uint32_t dst, const void* src) {
    asm volatile("cp.async.ca.shared.global [%0], [%1], 8;" :: "r"(dst), "l"(src));
}
__device__ __forceinline__ void ldsm_x4(uint32_t* r, uint32_t addr) {
    asm volatile("ldmatrix.sync.aligned.m8n8.x4.shared.b16 {%0,%1,%2,%3}, [%4];"
                 : "=r"(r[0]), "=r"(r[1]), "=r"(r[2]), "=r"(r[3]) : "r"(addr));
}
__device__ __forceinline__ void mma16816(float* d, const uint32_t* a, const uint32_t* b) {
    asm volatile(
        "mma.sync.aligned.m16n8k16.row.col.f32.bf16.bf16.f32 "
        "{%0,%1,%2,%3}, {%4,%5,%6,%7}, {%8,%9}, {%0,%1,%2,%3};"
        : "+f"(d[0]), "+f"(d[1]), "+f"(d[2]), "+f"(d[3])
        : "r"(a[0]), "r"(a[1]), "r"(a[2]), "r"(a[3]), "r"(b[0]), "r"(b[1]));
}
__device__ __forceinline__ float softplus_f(float x) {
    float e = exp2f(fabsf(x) * -1.44269504f);
    return fmaxf(x, 0.0f) + 0.69314718f * __log2f(1.0f + e);
}

// ----------------------------------------------------------- prep kernels
// fused A+B bf16 conversion: blocks [0,4096) -> B rows, [4096,4608) -> A rows.
// 4 rows per block, 96 threads per row; float4 load -> 4x bf16 (8B) store.
__global__ void __launch_bounds__(384)
conv_kernel(const float* __restrict__ x, const float* __restrict__ iv,
            const float* __restrict__ temb,
            const float* __restrict__ Wa, const float* __restrict__ Wi,
            const float* __restrict__ Wt)
{
    const int tid = threadIdx.x;
    const int r = tid / 96;
    const int c = (tid - r * 96) * 4;
    float4 v;
    __nv_bfloat16* dst;
    if (blockIdx.x < 4096) {
        const int j = blockIdx.x * 4 + r;
        if (c < 256)      v = *(const float4*)(Wa + (size_t)j * 256 + c);
        else if (c < 320) v = *(const float4*)(Wi + (size_t)j * 64 + (c - 256));
        else              v = *(const float4*)(Wt + (size_t)j * 64 + (c - 320));
        dst = g_B2 + (size_t)j * K2 + c;
    } else {
        const int bt = (blockIdx.x - 4096) * 4 + r;
        if (c < 256)      v = *(const float4*)(x + bt * 256 + c);
        else if (c < 320) v = *(const float4*)(iv + bt * 64 + (c - 256));
        else              v = *(const float4*)(temb + (bt & 127) * 64 + (c - 320));
        dst = g_A2 + (size_t)bt * K2 + c;
    }
    __nv_bfloat162 p0 = __float22bfloat162_rn(make_float2(v.x, v.y));
    __nv_bfloat162 p1 = __float22bfloat162_rn(make_float2(v.z, v.w));
    uint2 packed = make_uint2(*(uint32_t*)&p0, *(uint32_t*)&p1);
    *(uint2*)dst = packed;
}

__global__ void __launch_bounds__(128)
precompute_kernel(const float* __restrict__ temb,
                  const float* __restrict__ tW3, const float* __restrict__ tb3,
                  const float* __restrict__ tW2, const float* __restrict__ tb2,
                  const float* __restrict__ tW1, const float* __restrict__ tb1)
{
    __shared__ __align__(16) float semb[16 * 64];
    const int tid = threadIdx.x;
    const int t0  = blockIdx.y * 16;
    for (int i = tid; i < 256; i += 128)
        ((float4*)semb)[i] = ((const float4*)(temb + t0 * 64))[i];
    __syncthreads();

    const int col = blockIdx.x * 128 + tid;   // 0..5375
    const float* wrow; float bias; float* outb; int ostride;
    if (col < 4096)      { wrow = tW3 + col * 64; bias = tb3[col]; outb = g_tp3 + col; ostride = 4096; }
    else if (col < 5120) { int c = col - 4096; wrow = tW2 + c * 64; bias = tb2[c]; outb = g_tp2 + c; ostride = 1024; }
    else                 { int c = col - 5120; wrow = tW1 + c * 64; bias = tb1[c]; outb = g_tp1 + c; ostride = 256;  }

    float w[64];
    #pragma unroll
    for (int i = 0; i < 16; i++) ((float4*)w)[i] = ((const float4*)wrow)[i];

    for (int tt = 0; tt < 16; tt++) {
        const float* e = semb + tt * 64;
        float a0 = bias, a1 = 0.f, a2 = 0.f, a3 = 0.f;
        #pragma unroll
        for (int k = 0; k < 64; k += 4) {
            a0 += e[k] * w[k];     a1 += e[k+1] * w[k+1];
            a2 += e[k+2] * w[k+2]; a3 += e[k+3] * w[k+3];
        }
        outb[(size_t)(t0 + tt) * ostride] = (a0 + a1) + (a2 + a3);
    }
}

// ------------------------------------------------------------ main kernel
// grid (128 n-tiles, 16 m-tiles), 256 threads; CTA tile 128x128, K=384.
// 3-stage cp.async pipeline (one barrier per chunk), 2 CTAs/SM.
__global__ void __launch_bounds__(256, 2)
main_kernel(const float* __restrict__ w3, const float* __restrict__ w2,
            const float* __restrict__ w1, const float* __restrict__ ba,
            float* __restrict__ out)
{
    extern __shared__ char dyn_smem[];
    const uint32_t smb = smem_u32(dyn_smem);

    const int tid  = threadIdx.x;
    const int lane = tid & 31, wid = tid >> 5;
    const int warp_m = wid & 3, warp_n = wid >> 2;
    const int j0  = blockIdx.x * 128;
    const int bt0 = blockIdx.y * 128;
    const int node0 = blockIdx.x * 2;

    // ---- stage loader ----
    auto load_stage = [&](int kc, int s) {
        const uint32_t base = smb + s * STAGE_B;
        const int kof = kc * 64;
        #pragma unroll
        for (int q = 0; q < 4; q++) {               // A: 128 rows x 128B
            int id = tid + q * 256;
            int row = id >> 3, ch = id & 7;
            cp_async16(base + row * 128 + ((ch ^ (row & 7)) * 16),
                       g_A2 + (size_t)(bt0 + row) * K2 + kof + ch * 8);
        }
        #pragma unroll
        for (int q = 0; q < 4; q++) {               // B: 128 rows x 128B
            int id = tid + q * 256;
            int row = id >> 3, ch = id & 7;
            cp_async16(base + 16384 + row * 128 + ((ch ^ (row & 7)) * 16),
                       g_B2 + (size_t)(j0 + row) * K2 + kof + ch * 8);
        }
        asm volatile("cp.async.commit_group;" ::: "memory");
    };

    // ---- epilogue-table loader (into stage-0 region, post-drain) ----
    auto load_tables = [&]() {
        #pragma unroll
        for (int q = 0; q < 4; q++) {               // tp3: 1024 x cp16
            int id = tid + q * 256;
            int t = id >> 3, nl = (id >> 2) & 1, sub = id & 3;
            cp_async16(smb + EOFF_TP3 + t * 144 + nl * 64 + sub * 16,
                       g_tp3 + (size_t)t * 4096 + (node0 + nl) * 16 + sub * 4);
        }
        {                                           // tp2: 256 x cp16
            int t = tid >> 1, nl = tid & 1;
            cp_async16(smb + EOFF_TP2 + t * 48 + nl * 16,
                       g_tp2 + (size_t)t * 1024 + (node0 + nl) * 4);
        }
        if (tid < 128)                              // tp1: 128 x cp8
            cp_async8(smb + EOFF_TP1 + tid * 16, g_tp1 + (size_t)tid * 256 + node0);
        if (tid >= 128 && tid < 160)
            cp_async16(smb + EOFF_W3 + (tid - 128) * 16, w3 + node0 * 64 + (tid - 128) * 4);
        if (tid >= 160 && tid < 192)
            cp_async16(smb + EOFF_BA + (tid - 160) * 16, ba + j0 + (tid - 160) * 4);
        if (tid >= 192 && tid < 200)
            cp_async16(smb + EOFF_W2 + (tid - 192) * 16, w2 + node0 * 16 + (tid - 192) * 4);
        if (tid >= 200 && tid < 202)
            cp_async16(smb + EOFF_W1 + (tid - 200) * 16, w1 + node0 * 4 + (tid - 200) * 4);
        asm volatile("cp.async.commit_group;" ::: "memory");
    };

    load_stage(0, 0);
    load_stage(1, 1);

    float acc[2][8][4];
    #pragma unroll
    for (int mg = 0; mg < 2; mg++)
        #pragma unroll
        for (int ng = 0; ng < 8; ng++)
            #pragma unroll
            for (int r = 0; r < 4; r++) acc[mg][ng][r] = 0.f;

    const int a_row = warp_m * 32 + (lane & 15);
    const int a_half = (lane >> 4) & 1;
    const int b_row = warp_n * 64 + ((lane >> 4) & 1) * 8 + (lane & 7);
    const int b_half = (lane >> 3) & 1;

    for (int kc = 0; kc < KC_CHUNKS; kc++) {
        asm volatile("cp.async.wait_group 1;" ::: "memory");
        __syncthreads();                            // stage kc resident; stage (kc-1)%3 drained
        if (kc + 2 < KC_CHUNKS)       load_stage(kc + 2, (kc + 2) % NSTAGE);
        else if (kc + 2 == KC_CHUNKS) load_tables();   // kc == 4: stage 0 free

        const uint32_t sA = smb + (kc % NSTAGE) * STAGE_B;
        const uint32_t sB = sA + 16384;
        #pragma unroll
        for (int kk = 0; kk < 4; kk++) {
            uint32_t af[2][4], bf[4][4];
            #pragma unroll
            for (int mg = 0; mg < 2; mg++) {
                int row = a_row + mg * 16;
                ldsm_x4(af[mg], sA + row * 128 + (((kk * 2 + a_half) ^ (row & 7)) * 16));
            }
            #pragma unroll
            for (int n2 = 0; n2 < 4; n2++) {
                int row = b_row + n2 * 16;
                ldsm_x4(bf[n2], sB + row * 128 + (((kk * 2 + b_half) ^ (row & 7)) * 16));
            }
            #pragma unroll
            for (int mg = 0; mg < 2; mg++)
                #pragma unroll
                for (int ng = 0; ng < 8; ng++)
                    mma16816(acc[mg][ng], af[mg], bf[ng >> 1] + (ng & 1) * 2);
        }
    }

    asm volatile("cp.async.wait_group 0;" ::: "memory");
    __syncthreads();                                // tables resident for all threads

    // ---- register-level tree epilogue ----
    const float* sTP3 = (const float*)(dyn_smem + EOFF_TP3);
    const float* sTP2 = (const float*)(dyn_smem + EOFF_TP2);
    const float* sTP1 = (const float*)(dyn_smem + EOFF_TP1);
    const float* sW3  = (const float*)(dyn_smem + EOFF_W3);
    const float* sBA  = (const float*)(dyn_smem + EOFF_BA);
    const float* sW2  = (const float*)(dyn_smem + EOFF_W2);
    const float* sW1  = (const float*)(dyn_smem + EOFF_W1);

    const int b_  = (lane >> 1) & 1;
    const int q_  = lane >> 2;
    float res[4];

    #pragma unroll
    for (int mg = 0; mg < 2; mg++)
        #pragma unroll
        for (int h = 0; h < 2; h++) {
            const int row = warp_m * 32 + mg * 16 + h * 8 + q_;   // == t for this bt
            float a3loc[8];
            #pragma unroll
            for (int ng = 0; ng < 8; ng++) {
                int col0 = warp_n * 64 + ng * 8 + 2 * (lane & 3);
                float p = sW3[col0]     * softplus_f(acc[mg][ng][h * 2]     + sBA[col0])
                        + sW3[col0 + 1] * softplus_f(acc[mg][ng][h * 2 + 1] + sBA[col0 + 1]);
                p += __shfl_xor_sync(0xffffffffu, p, 1);
                a3loc[ng] = softplus_f(p + sTP3[row * 36 + warp_n * 16 + 2 * ng + b_]);
            }
            float a2v[4];
            #pragma unroll
            for (int i3 = 0; i3 < 4; i3++) {
                float p = sW2[warp_n * 16 + i3 * 4 + b_]     * a3loc[2 * i3]
                        + sW2[warp_n * 16 + i3 * 4 + 2 + b_] * a3loc[2 * i3 + 1];
                p += __shfl_xor_sync(0xffffffffu, p, 2);
                a2v[i3] = softplus_f(p + sTP2[row * 12 + warp_n * 4 + i3]);
            }
            float s = sTP1[row * 4 + warp_n];
            #pragma unroll
            for (int i3 = 0; i3 < 4; i3++) s += sW1[warp_n * 4 + i3] * a2v[i3];
            res[mg * 2 + h] = softplus_f(s);
        }

    const int sel = lane & 3;
    const int rowsel = warp_m * 32 + (sel >> 1) * 16 + (sel & 1) * 8 + q_;
    out[(size_t)(bt0 + rowsel) * 256 + node0 + warp_n] = res[sel];
}

// ---------------------------------------------------------------------------
extern "C" void kernel_launch(void* const* d_in, const int* in_sizes, int n_in,
                              void* d_out, int out_size)
{
    const float* x    = (const float*)d_in[0];
    const float* temb = (const float*)d_in[1];
    const float* iv   = (const float*)d_in[2];
    const float* Wa   = (const float*)d_in[3];
    const float* ba   = (const float*)d_in[4];
    const float* Wt   = (const float*)d_in[5];
    const float* Wi   = (const float*)d_in[6];
    const float* w3   = (const float*)d_in[7];
    const float* tW3  = (const float*)d_in[8];
    const float* tb3  = (const float*)d_in[9];
    const float* w2   = (const float*)d_in[10];
    const float* tW2  = (const float*)d_in[11];
    const float* tb2  = (const float*)d_in[12];
    const float* w1   = (const float*)d_in[13];
    const float* tW1  = (const float*)d_in[14];
    const float* tb1  = (const float*)d_in[15];
    float* out = (float*)d_out;

    static bool attr_set = false;
    if (!attr_set) {
        cudaFuncSetAttribute(main_kernel, cudaFuncAttributeMaxDynamicSharedMemorySize, SMEM_REQ);
        attr_set = true;
    }

    conv_kernel<<<4608, 384>>>(x, iv, temb, Wa, Wi, Wt);
    precompute_kernel<<<dim3(42, 8), 128>>>(temb, tW3, tb3, tW2, tb2, tW1, tb1);
    main_kernel<<<dim3(128, 16), 256, SMEM_REQ>>>(w3, w2, w1, ba, out);
}

// round 13
// speedup vs baseline: 1.0971x; 1.0571x over previous
#include <cuda_runtime.h>
#include <cuda_fp16.h>
#include <cstdint>

// ============================================================================
// DendriticResidualModel — mma.sync fp16 (f16 ACCUM = 2x HMMA rate), K=384,
// 3-stage cp.async pipeline, late-loaded epilogue tables, register tree.
//   pre[bt,j] = x·Wa^T + iv·Wi^T + temb·Wt^T + ba,  t = bt & 127
// ============================================================================

#define NUM_NODES 16384
#define BT_ROWS   2048
#define K2        384
#define KC_CHUNKS 6           // 384 / 64
#define STAGE_B   32768       // A 16KB + B 16KB per stage
#define NSTAGE    3
#define SMEM_REQ  (NSTAGE * STAGE_B)   // 98304

// epilogue tables live in stage-0 region (loaded after GEMM drains it)
#define EOFF_TP3  0           // 128 * 144 = 18432
#define EOFF_TP2  18432       // 128 * 48  = 6144
#define EOFF_TP1  24576       // 128 * 16  = 2048
#define EOFF_W3   26624       // 512
#define EOFF_BA   27136       // 512
#define EOFF_W2   27648       // 128
#define EOFF_W1   27776       // 32

__device__ __align__(16) __half g_A2[BT_ROWS * K2];      // 1.5 MB
__device__ __align__(16) __half g_B2[NUM_NODES * K2];    // 12.6 MB
__device__ __align__(16) float g_tp3[128 * 4096];
__device__ __align__(16) float g_tp2[128 * 1024];
__device__ __align__(16) float g_tp1[128 * 256];

// ---------------------------------------------------------------- helpers
__device__ __forceinline__ uint32_t smem_u32(const void* p) {
    uint32_t a;
    asm("{ .reg .u64 t; cvta.to.shared.u64 t, %1; cvt.u32.u64 %0, t; }" : "=r"(a) : "l"(p));
    return a;
}
__device__ __forceinline__ void cp_async16(uint32_t dst, const void* src) {
    asm volatile("cp.async.cg.shared.global [%0], [%1], 16;" :: "r"(dst), "l"(src));
}
__device__ __forceinline__ void cp_async8(uint32_t dst, const void* src) {
    asm volatile("cp.async.ca.shared.global [%0], [%1], 8;" :: "r"(dst), "l"(src));
}
__device__ __forceinline__ void ldsm_x4(uint32_t* r, uint32_t addr) {
    asm volatile("ldmatrix.sync.aligned.m8n8.x4.shared.b16 {%0,%1,%2,%3}, [%4];"
                 : "=r"(r[0]), "=r"(r[1]), "=r"(r[2]), "=r"(r[3]) : "r"(addr));
}
// fp16 inputs, fp16 accumulator (2x rate vs f32 accum on register-path HMMA)
__device__ __forceinline__ void mma16816h(uint32_t* d, const uint32_t* a, const uint32_t* b) {
    asm volatile(
        "mma.sync.aligned.m16n8k16.row.col.f16.f16.f16.f16 "
        "{%0,%1}, {%2,%3,%4,%5}, {%6,%7}, {%0,%1};"
        : "+r"(d[0]), "+r"(d[1])
        : "r"(a[0]), "r"(a[1]), "r"(a[2]), "r"(a[3]), "r"(b[0]), "r"(b[1]));
}
__device__ __forceinline__ float softplus_f(float x) {
    float e = exp2f(fabsf(x) * -1.44269504f);
    return fmaxf(x, 0.0f) + 0.69314718f * __log2f(1.0f + e);
}

// ----------------------------------------------------------- prep kernels
// fused A+B fp16 conversion: blocks [0,4096) -> B rows, [4096,4608) -> A rows.
__global__ void __launch_bounds__(384)
conv_kernel(const float* __restrict__ x, const float* __restrict__ iv,
            const float* __restrict__ temb,
            const float* __restrict__ Wa, const float* __restrict__ Wi,
            const float* __restrict__ Wt)
{
    const int tid = threadIdx.x;
    const int r = tid / 96;
    const int c = (tid - r * 96) * 4;
    float4 v;
    __half* dst;
    if (blockIdx.x < 4096) {
        const int j = blockIdx.x * 4 + r;
        if (c < 256)      v = *(const float4*)(Wa + (size_t)j * 256 + c);
        else if (c < 320) v = *(const float4*)(Wi + (size_t)j * 64 + (c - 256));
        else              v = *(const float4*)(Wt + (size_t)j * 64 + (c - 320));
        dst = g_B2 + (size_t)j * K2 + c;
    } else {
        const int bt = (blockIdx.x - 4096) * 4 + r;
        if (c < 256)      v = *(const float4*)(x + bt * 256 + c);
        else if (c < 320) v = *(const float4*)(iv + bt * 64 + (c - 256));
        else              v = *(const float4*)(temb + (bt & 127) * 64 + (c - 320));
        dst = g_A2 + (size_t)bt * K2 + c;
    }
    __half2 p0 = __float22half2_rn(make_float2(v.x, v.y));
    __half2 p1 = __float22half2_rn(make_float2(v.z, v.w));
    uint2 packed = make_uint2(*(uint32_t*)&p0, *(uint32_t*)&p1);
    *(uint2*)dst = packed;
}

__global__ void __launch_bounds__(128)
precompute_kernel(const float* __restrict__ temb,
                  const float* __restrict__ tW3, const float* __restrict__ tb3,
                  const float* __restrict__ tW2, const float* __restrict__ tb2,
                  const float* __restrict__ tW1, const float* __restrict__ tb1)
{
    __shared__ __align__(16) float semb[16 * 64];
    const int tid = threadIdx.x;
    const int t0  = blockIdx.y * 16;
    for (int i = tid; i < 256; i += 128)
        ((float4*)semb)[i] = ((const float4*)(temb + t0 * 64))[i];
    __syncthreads();

    const int col = blockIdx.x * 128 + tid;   // 0..5375
    const float* wrow; float bias; float* outb; int ostride;
    if (col < 4096)      { wrow = tW3 + col * 64; bias = tb3[col]; outb = g_tp3 + col; ostride = 4096; }
    else if (col < 5120) { int c = col - 4096; wrow = tW2 + c * 64; bias = tb2[c]; outb = g_tp2 + c; ostride = 1024; }
    else                 { int c = col - 5120; wrow = tW1 + c * 64; bias = tb1[c]; outb = g_tp1 + c; ostride = 256;  }

    float w[64];
    #pragma unroll
    for (int i = 0; i < 16; i++) ((float4*)w)[i] = ((const float4*)wrow)[i];

    for (int tt = 0; tt < 16; tt++) {
        const float* e = semb + tt * 64;
        float a0 = bias, a1 = 0.f, a2 = 0.f, a3 = 0.f;
        #pragma unroll
        for (int k = 0; k < 64; k += 4) {
            a0 += e[k] * w[k];     a1 += e[k+1] * w[k+1];
            a2 += e[k+2] * w[k+2]; a3 += e[k+3] * w[k+3];
        }
        outb[(size_t)(t0 + tt) * ostride] = (a0 + a1) + (a2 + a3);
    }
}

// ------------------------------------------------------------ main kernel
// grid (128 n-tiles, 16 m-tiles), 256 threads; CTA tile 128x128, K=384.
// 3-stage cp.async pipeline, 2 CTAs/SM, f16 accumulators.
__global__ void __launch_bounds__(256, 2)
main_kernel(const float* __restrict__ w3, const float* __restrict__ w2,
            const float* __restrict__ w1, const float* __restrict__ ba,
            float* __restrict__ out)
{
    extern __shared__ char dyn_smem[];
    const uint32_t smb = smem_u32(dyn_smem);

    const int tid  = threadIdx.x;
    const int lane = tid & 31, wid = tid >> 5;
    const int warp_m = wid & 3, warp_n = wid >> 2;
    const int j0  = blockIdx.x * 128;
    const int bt0 = blockIdx.y * 128;
    const int node0 = blockIdx.x * 2;

    // ---- stage loader ----
    auto load_stage = [&](int kc, int s) {
        const uint32_t base = smb + s * STAGE_B;
        const int kof = kc * 64;
        #pragma unroll
        for (int q = 0; q < 4; q++) {               // A: 128 rows x 128B
            int id = tid + q * 256;
            int row = id >> 3, ch = id & 7;
            cp_async16(base + row * 128 + ((ch ^ (row & 7)) * 16),
                       g_A2 + (size_t)(bt0 + row) * K2 + kof + ch * 8);
        }
        #pragma unroll
        for (int q = 0; q < 4; q++) {               // B: 128 rows x 128B
            int id = tid + q * 256;
            int row = id >> 3, ch = id & 7;
            cp_async16(base + 16384 + row * 128 + ((ch ^ (row & 7)) * 16),
                       g_B2 + (size_t)(j0 + row) * K2 + kof + ch * 8);
        }
        asm volatile("cp.async.commit_group;" ::: "memory");
    };

    // ---- epilogue-table loader (into stage-0 region, post-drain) ----
    auto load_tables = [&]() {
        #pragma unroll
        for (int q = 0; q < 4; q++) {               // tp3: 1024 x cp16
            int id = tid + q * 256;
            int t = id >> 3, nl = (id >> 2) & 1, sub = id & 3;
            cp_async16(smb + EOFF_TP3 + t * 144 + nl * 64 + sub * 16,
                       g_tp3 + (size_t)t * 4096 + (node0 + nl) * 16 + sub * 4);
        }
        {                                           // tp2: 256 x cp16
            int t = tid >> 1, nl = tid & 1;
            cp_async16(smb + EOFF_TP2 + t * 48 + nl * 16,
                       g_tp2 + (size_t)t * 1024 + (node0 + nl) * 4);
        }
        if (tid < 128)                              // tp1: 128 x cp8
            cp_async8(smb + EOFF_TP1 + tid * 16, g_tp1 + (size_t)tid * 256 + node0);
        if (tid >= 128 && tid < 160)
            cp_async16(smb + EOFF_W3 + (tid - 128) * 16, w3 + node0 * 64 + (tid - 128) * 4);
        if (tid >= 160 && tid < 192)
            cp_async16(smb + EOFF_BA + (tid - 160) * 16, ba + j0 + (tid - 160) * 4);
        if (tid >= 192 && tid < 200)
            cp_async16(smb + EOFF_W2 + (tid - 192) * 16, w2 + node0 * 16 + (tid - 192) * 4);
        if (tid >= 200 && tid < 202)
            cp_async16(smb + EOFF_W1 + (tid - 200) * 16, w1 + node0 * 4 + (tid - 200) * 4);
        asm volatile("cp.async.commit_group;" ::: "memory");
    };

    load_stage(0, 0);
    load_stage(1, 1);

    // f16x2 accumulators: [mg][ng][h]  h=0 -> rows 0-7 (c0,c1), h=1 -> rows 8-15
    uint32_t acc[2][8][2];
    #pragma unroll
    for (int mg = 0; mg < 2; mg++)
        #pragma unroll
        for (int ng = 0; ng < 8; ng++) { acc[mg][ng][0] = 0u; acc[mg][ng][1] = 0u; }

    const int a_row = warp_m * 32 + (lane & 15);
    const int a_half = (lane >> 4) & 1;
    const int b_row = warp_n * 64 + ((lane >> 4) & 1) * 8 + (lane & 7);
    const int b_half = (lane >> 3) & 1;

    for (int kc = 0; kc < KC_CHUNKS; kc++) {
        asm volatile("cp.async.wait_group 1;" ::: "memory");
        __syncthreads();                            // stage kc resident; stage (kc-1)%3 drained
        if (kc + 2 < KC_CHUNKS)       load_stage(kc + 2, (kc + 2) % NSTAGE);
        else if (kc + 2 == KC_CHUNKS) load_tables();   // kc == 4: stage 0 free

        const uint32_t sA = smb + (kc % NSTAGE) * STAGE_B;
        const uint32_t sB = sA + 16384;
        #pragma unroll
        for (int kk = 0; kk < 4; kk++) {
            uint32_t af[2][4], bf[4][4];
            #pragma unroll
            for (int mg = 0; mg < 2; mg++) {
                int row = a_row + mg * 16;
                ldsm_x4(af[mg], sA + row * 128 + (((kk * 2 + a_half) ^ (row & 7)) * 16));
            }
            #pragma unroll
            for (int n2 = 0; n2 < 4; n2++) {
                int row = b_row + n2 * 16;
                ldsm_x4(bf[n2], sB + row * 128 + (((kk * 2 + b_half) ^ (row & 7)) * 16));
            }
            #pragma unroll
            for (int mg = 0; mg < 2; mg++)
                #pragma unroll
                for (int ng = 0; ng < 8; ng++)
                    mma16816h(acc[mg][ng], af[mg], bf[ng >> 1] + (ng & 1) * 2);
        }
    }

    asm volatile("cp.async.wait_group 0;" ::: "memory");
    __syncthreads();                                // tables resident

    // ---- register-level tree epilogue ----
    const float* sTP3 = (const float*)(dyn_smem + EOFF_TP3);
    const float* sTP2 = (const float*)(dyn_smem + EOFF_TP2);
    const float* sTP1 = (const float*)(dyn_smem + EOFF_TP1);
    const float* sW3  = (const float*)(dyn_smem + EOFF_W3);
    const float* sBA  = (const float*)(dyn_smem + EOFF_BA);
    const float* sW2  = (const float*)(dyn_smem + EOFF_W2);
    const float* sW1  = (const float*)(dyn_smem + EOFF_W1);

    const int b_  = (lane >> 1) & 1;
    const int q_  = lane >> 2;
    float res[4];

    #pragma unroll
    for (int mg = 0; mg < 2; mg++)
        #pragma unroll
        for (int h = 0; h < 2; h++) {
            const int row = warp_m * 32 + mg * 16 + h * 8 + q_;   // == t for this bt
            float a3loc[8];
            #pragma unroll
            for (int ng = 0; ng < 8; ng++) {
                int col0 = warp_n * 64 + ng * 8 + 2 * (lane & 3);
                float2 c01 = __half22float2(*(const __half2*)&acc[mg][ng][h]);
                float p = sW3[col0]     * softplus_f(c01.x + sBA[col0])
                        + sW3[col0 + 1] * softplus_f(c01.y + sBA[col0 + 1]);
                p += __shfl_xor_sync(0xffffffffu, p, 1);
                a3loc[ng] = softplus_f(p + sTP3[row * 36 + warp_n * 16 + 2 * ng + b_]);
            }
            float a2v[4];
            #pragma unroll
            for (int i3 = 0; i3 < 4; i3++) {
                float p = sW2[warp_n * 16 + i3 * 4 + b_]     * a3loc[2 * i3]
                        + sW2[warp_n * 16 + i3 * 4 + 2 + b_] * a3loc[2 * i3 + 1];
                p += __shfl_xor_sync(0xffffffffu, p, 2);
                a2v[i3] = softplus_f(p + sTP2[row * 12 + warp_n * 4 + i3]);
            }
            float s = sTP1[row * 4 + warp_n];
            #pragma unroll
            for (int i3 = 0; i3 < 4; i3++) s += sW1[warp_n * 4 + i3] * a2v[i3];
            res[mg * 2 + h] = softplus_f(s);
        }

    const int sel = lane & 3;
    const int rowsel = warp_m * 32 + (sel >> 1) * 16 + (sel & 1) * 8 + q_;
    out[(size_t)(bt0 + rowsel) * 256 + node0 + warp_n] = res[sel];
}

// ---------------------------------------------------------------------------
extern "C" void kernel_launch(void* const* d_in, const int* in_sizes, int n_in,
                              void* d_out, int out_size)
{
    const float* x    = (const float*)d_in[0];
    const float* temb = (const float*)d_in[1];
    const float* iv   = (const float*)d_in[2];
    const float* Wa   = (const float*)d_in[3];
    const float* ba   = (const float*)d_in[4];
    const float* Wt   = (const float*)d_in[5];
    const float* Wi   = (const float*)d_in[6];
    const float* w3   = (const float*)d_in[7];
    const float* tW3  = (const float*)d_in[8];
    const float* tb3  = (const float*)d_in[9];
    const float* w2   = (const float*)d_in[10];
    const float* tW2  = (const float*)d_in[11];
    const float* tb2  = (const float*)d_in[12];
    const float* w1   = (const float*)d_in[13];
    const float* tW1  = (const float*)d_in[14];
    const float* tb1  = (const float*)d_in[15];
    float* out = (float*)d_out;

    static bool attr_set = false;
    if (!attr_set) {
        cudaFuncSetAttribute(main_kernel, cudaFuncAttributeMaxDynamicSharedMemorySize, SMEM_REQ);
        attr_set = true;
    }

    conv_kernel<<<4608, 384>>>(x, iv, temb, Wa, Wi, Wt);
    precompute_kernel<<<dim3(42, 8), 128>>>(temb, tW3, tb3, tW2, tb2, tW1, tb1);
    main_kernel<<<dim3(128, 16), 256, SMEM_REQ>>>(w3, w2, w1, ba, out);
}